// round 6
// baseline (speedup 1.0000x reference)
#include <cuda_runtime.h>
#include <cuda_bf16.h>
#include <cstdint>

#define B_ 4
#define T_ 2048
#define H_ 16
#define D_ 128
#define HD 2048        // H_*D_
#define S_ 16          // steps per chunk
#define NC (T_/S_)     // 128 chunks

// per-buffer float offsets (padded row tiles: 16 t * 160 floats)
#define FS 0
#define KS 2560        // raw k -> kg (in-place prepass)
#define QS 5120
#define GS 7680        // raw g rows (prepass input only)
#define VC 10240       // v cols -> vg (in-place)
#define GC 11264       // g cols
#define BUF_FLOATS 12288
#define BUF_BYTES  49152
#define SM_BYTES   98304   // 2 buffers

typedef unsigned long long u64;

__device__ __forceinline__ u64 pk2(float x, float y) {
    u64 r; asm("mov.b64 %0,{%1,%2};" : "=l"(r) : "f"(x), "f"(y)); return r;
}
__device__ __forceinline__ float2 up2(u64 a) {
    float2 r; asm("mov.b64 {%0,%1},%2;" : "=f"(r.x), "=f"(r.y) : "l"(a)); return r;
}
__device__ __forceinline__ u64 mul2(u64 a, u64 b) {
    u64 d; asm("mul.rn.f32x2 %0,%1,%2;" : "=l"(d) : "l"(a), "l"(b)); return d;
}
__device__ __forceinline__ u64 add2(u64 a, u64 b) {
    u64 d; asm("add.rn.f32x2 %0,%1,%2;" : "=l"(d) : "l"(a), "l"(b)); return d;
}
__device__ __forceinline__ u64 fma2(u64 a, u64 b, u64 c) {
    u64 d; asm("fma.rn.f32x2 %0,%1,%2,%3;" : "=l"(d) : "l"(a), "l"(b), "l"(c)); return d;
}
__device__ __forceinline__ u64 max2c(u64 a, float c) {
    float2 t = up2(a);
    t.x = fmaxf(t.x, c); t.y = fmaxf(t.y, c);
    return pk2(t.x, t.y);
}
__device__ __forceinline__ void cp16(uint32_t dst, const float* src) {
    asm volatile("cp.async.cg.shared.global [%0], [%1], 16;" :: "r"(dst), "l"(src) : "memory");
}
__device__ __forceinline__ uint32_t s2u(const void* p) {
    uint32_t a;
    asm("{ .reg .u64 t; cvta.to.shared.u64 t, %1; cvt.u32.u64 %0, t; }" : "=r"(a) : "l"(p));
    return a;
}

// Row tile per t: 8 blocks of (16 floats + 4 pad) = 160 floats.
// Granule a (rows 4a..4a+3) at t*160 + (a>>2)*20 + (a&3)*4 -> conflict-free LDS.128.
__global__ __launch_bounds__(512, 1) void delta_kernel(
    const float* __restrict__ q, const float* __restrict__ k,
    const float* __restrict__ v, const float* __restrict__ f,
    const float* __restrict__ g, float* __restrict__ out)
{
    extern __shared__ float smp[];
    const uint32_t smem0 = s2u(smp);

    const int tid  = threadIdx.x;
    const int w    = tid >> 5, lane = tid & 31;
    const int r    = lane >> 2;          // 8 row-groups of 16 rows
    const int c    = lane & 3;           // 4 columns per warp
    const int colbase = blockIdx.x * 64;
    const long base0  = (long)blockIdx.z * T_ * HD + (long)blockIdx.y * D_;

    // ---- cp.async roles: 5 granules (16B) per thread per chunk ----
    const int  t_s = tid >> 5, gi = tid & 31;                 // rows: (t, 16B granule)
    const long growb = base0 + (long)t_s * HD + gi * 4;
    const bool isv = (tid < 256);                             // cols: v | g
    const int  ct = (tid & 255) >> 4, ci = tid & 15;
    const long gcolb = base0 + (long)ct * HD + colbase + ci * 4;
    const uint32_t d_row = (uint32_t)((t_s * 160 + (gi >> 2) * 20 + (gi & 3) * 4) * 4);
    const uint32_t d_col = (uint32_t)(((isv ? VC : GC) + ct * 64 + ci * 4) * 4);
    const float* colsrc = isv ? v : g;

    // compute-phase constants
    const int rl  = r * 20;
    const int dj  = colbase + w * 4 + c;                  // global column
    const int fcidx = (dj >> 4) * 20 + (dj & 15);
    const int vcidx = w * 4 + c;
    float* outp = out + base0 + dj;

    // state: 16 rows x 1 col = 8 packed f32x2
    u64 M[8];
#pragma unroll
    for (int p = 0; p < 8; p++) M[p] = 0ull;

    // prime: cp chunk 0 -> buffer 0
    {
        cp16(smem0 + FS * 4 + d_row, f + growb);
        cp16(smem0 + KS * 4 + d_row, k + growb);
        cp16(smem0 + QS * 4 + d_row, q + growb);
        cp16(smem0 + GS * 4 + d_row, g + growb);
        cp16(smem0 + d_col, colsrc + gcolb);
        asm volatile("cp.async.commit_group;" ::: "memory");
    }

    for (int ch = 0; ch < NC; ch++) {
        float* buf = smp + (ch & 1) * BUF_FLOATS;
        asm volatile("cp.async.wait_group 0;" ::: "memory");
        __syncthreads();
        // ---- prepass: kg = k*g, vg = v*g (in place, thread-local slots) ----
#pragma unroll
        for (int i = 0; i < 5; i++) {
            const int idx = tid + i * 512;
            buf[KS + idx] *= buf[GS + idx];
        }
#pragma unroll
        for (int i = 0; i < 2; i++) {
            const int idx = tid + i * 512;
            buf[VC + idx] *= buf[GC + idx];
        }
        // ---- issue cp for next chunk (overlaps compute) ----
        if (ch + 1 < NC) {
            const uint32_t b = smem0 + (uint32_t)((ch + 1) & 1) * BUF_BYTES;
            const long off = (long)(ch + 1) * S_ * HD;
            cp16(b + FS * 4 + d_row, f + growb + off);
            cp16(b + KS * 4 + d_row, k + growb + off);
            cp16(b + QS * 4 + d_row, q + growb + off);
            cp16(b + GS * 4 + d_row, g + growb + off);
            cp16(b + d_col, colsrc + gcolb + off);
            asm volatile("cp.async.commit_group;" ::: "memory");
        }
        __syncthreads();   // prepass results visible to all
        // ---- compute 16 steps ----
#pragma unroll
        for (int s = 0; s < S_; s++) {
            const float* fb = buf + FS + s * 160 + rl;
            const float* kb = buf + KS + s * 160 + rl;
            const float* qb = buf + QS + s * 160 + rl;
            const float fc  = buf[FS + s * 160 + fcidx];
            const float vgc = buf[VC + s * 64 + vcidx];
            const u64 fj = pk2(fc, fc);
            const u64 vj = pk2(vgc, vgc);
            u64 oa = 0ull, ob = 0ull;
#pragma unroll
            for (int l = 0; l < 4; l++) {
                float4 f4 = *(const float4*)(fb + l * 4);
                float4 k4 = *(const float4*)(kb + l * 4);
                float4 q4 = *(const float4*)(qb + l * 4);
                u64 fo, wv;
                fo = max2c(mul2(pk2(f4.x, f4.y), fj), 0.8f);
                wv = mul2(pk2(k4.x, k4.y), vj);
                M[l * 2] = fma2(M[l * 2], fo, wv);
                oa = fma2(pk2(q4.x, q4.y), M[l * 2], oa);
                fo = max2c(mul2(pk2(f4.z, f4.w), fj), 0.8f);
                wv = mul2(pk2(k4.z, k4.w), vj);
                M[l * 2 + 1] = fma2(M[l * 2 + 1], fo, wv);
                ob = fma2(pk2(q4.z, q4.w), M[l * 2 + 1], ob);
            }
            const float2 oo = up2(add2(oa, ob));
            float osum = oo.x + oo.y;
            osum += __shfl_xor_sync(0xffffffffu, osum, 4);
            osum += __shfl_xor_sync(0xffffffffu, osum, 8);
            osum += __shfl_xor_sync(0xffffffffu, osum, 16);
            if (lane < 4) outp[s * HD] = osum;
        }
        outp += S_ * HD;
        __syncthreads();   // compute done before next chunk's prepass touches buf
    }
}

extern "C" void kernel_launch(void* const* d_in, const int* in_sizes, int n_in,
                              void* d_out, int out_size) {
    const float* q = (const float*)d_in[0];
    const float* k = (const float*)d_in[1];
    const float* v = (const float*)d_in[2];
    const float* f = (const float*)d_in[3];
    const float* g = (const float*)d_in[4];
    cudaFuncSetAttribute(delta_kernel,
                         cudaFuncAttributeMaxDynamicSharedMemorySize, SM_BYTES);
    dim3 grid(2, H_, B_);
    delta_kernel<<<grid, 512, SM_BYTES>>>(q, k, v, f, g, (float*)d_out);
}